// round 15
// baseline (speedup 1.0000x reference)
#include <cuda_runtime.h>
#include <cuda_bf16.h>
#include <math.h>
#include <stdint.h>

// ---------------- problem constants ----------------
#define MAX_NODES 100000
#define MAX_EDGES 2000000
#define D_IN  256
#define D_HID 256
#define D_CLS 64
#define KDIM  256
#define KW    (KDIM / 2)   // packed bf16x2 words per row

// ---------------- scratch (static, no allocs) ----------------
__device__ float    g_h1  [(size_t)MAX_NODES * D_HID];
__device__ float    g_h2  [(size_t)MAX_NODES * D_CLS];
__device__ uint32_t g_xhi [(size_t)MAX_NODES * KW];
__device__ uint32_t g_xlo [(size_t)MAX_NODES * KW];
__device__ uint32_t g_a1hi[(size_t)MAX_NODES * KW];
__device__ uint32_t g_a1lo[(size_t)MAX_NODES * KW];
__device__ uint32_t g_w1hi[D_HID * KW], g_w1lo[D_HID * KW];
__device__ uint32_t g_w2hi[D_CLS * KW], g_w2lo[D_CLS * KW];
__device__ float    g_dinv[MAX_NODES];
__device__ int      g_cnt [MAX_NODES];
__device__ int      g_off [MAX_NODES];
__device__ int      g_cur [MAX_NODES];
__device__ int      g_srcsort[MAX_EDGES];
__device__ int      g_bsum[1024];
__device__ int      g_boff[1024];

// ---------------- helpers ----------------
__device__ __forceinline__ void split2_bf16(float2 v, uint32_t& hi, uint32_t& lo) {
    __nv_bfloat16 hx = __float2bfloat16(v.x);
    __nv_bfloat16 hy = __float2bfloat16(v.y);
    __nv_bfloat16 lx = __float2bfloat16(v.x - __bfloat162float(hx));
    __nv_bfloat16 ly = __float2bfloat16(v.y - __bfloat162float(hy));
    hi = (uint32_t)__bfloat16_as_ushort(hx) | ((uint32_t)__bfloat16_as_ushort(hy) << 16);
    lo = (uint32_t)__bfloat16_as_ushort(lx) | ((uint32_t)__bfloat16_as_ushort(ly) << 16);
}

__device__ __forceinline__ void cp_async16(uint32_t dst, const void* src, bool pred) {
    int sz = pred ? 16 : 0;
    asm volatile("cp.async.cg.shared.global [%0], [%1], 16, %2;"
                 :: "r"(dst), "l"(src), "r"(sz) : "memory");
}

__device__ __forceinline__ void ldsm_x4(uint32_t r[4], uint32_t addr) {
    asm volatile("ldmatrix.sync.aligned.m8n8.x4.shared.b16 {%0,%1,%2,%3}, [%4];"
                 : "=r"(r[0]), "=r"(r[1]), "=r"(r[2]), "=r"(r[3]) : "r"(addr));
}

__device__ __forceinline__ void mma_bf16(float c[4], const uint32_t a[4],
                                         uint32_t b0, uint32_t b1) {
    asm volatile(
        "mma.sync.aligned.m16n8k16.row.col.f32.bf16.bf16.f32 "
        "{%0,%1,%2,%3}, {%4,%5,%6,%7}, {%8,%9}, {%0,%1,%2,%3};"
        : "+f"(c[0]), "+f"(c[1]), "+f"(c[2]), "+f"(c[3])
        : "r"(a[0]), "r"(a[1]), "r"(a[2]), "r"(a[3]), "r"(b0), "r"(b1));
}

// swizzled byte offset: 64B rows of 4x16B chunks, chunk column permuted by row
// so each ldmatrix phase (8 consecutive rows) hits 8 distinct 16B bank-groups.
__device__ __forceinline__ uint32_t swz(int row, int q) {
    return (uint32_t)(row * 64 + ((q ^ ((row >> 1) & 3)) * 16));
}

// ---------------- pre-split kernels ----------------
__global__ void split_x(const float* __restrict__ x, uint32_t* __restrict__ xhi,
                        uint32_t* __restrict__ xlo, int* __restrict__ cnt,
                        int n, long nw) {
    long i0 = (long)blockIdx.x * blockDim.x + threadIdx.x;
    if (i0 < n) cnt[i0] = 0;
    long stride = (long)gridDim.x * blockDim.x;
    for (long i = i0; i < nw; i += stride) {
        float2 v = ((const float2*)x)[i];
        uint32_t hi, lo;
        split2_bf16(v, hi, lo);
        xhi[i] = hi;
        xlo[i] = lo;
    }
}

__global__ void split_w(const float* __restrict__ W1, const float* __restrict__ W2,
                        uint32_t* w1hi, uint32_t* w1lo,
                        uint32_t* w2hi, uint32_t* w2lo) {
    int i = blockIdx.x * 256 + threadIdx.x;
    if (i < D_HID * KW) {
        int nn = i >> 7, w = i & (KW - 1);
        float2 v = make_float2(W1[(2 * w) * D_HID + nn], W1[(2 * w + 1) * D_HID + nn]);
        uint32_t hi, lo;
        split2_bf16(v, hi, lo);
        w1hi[i] = hi; w1lo[i] = lo;
    } else if (i < D_HID * KW + D_CLS * KW) {
        int j = i - D_HID * KW;
        int nn = j >> 7, w = j & (KW - 1);
        float2 v = make_float2(W2[(2 * w) * D_CLS + nn], W2[(2 * w + 1) * D_CLS + nn]);
        uint32_t hi, lo;
        split2_bf16(v, hi, lo);
        w2hi[j] = hi; w2lo[j] = lo;
    }
}

// ---------------- CSR build ----------------
__global__ void count_dst(const int* __restrict__ dst, int* cnt, int E) {
    int e = blockIdx.x * blockDim.x + threadIdx.x;
    if (e < E) atomicAdd(&cnt[dst[e]], 1);
}

__global__ void block_sums(const int* __restrict__ cnt, int* bsum, int n) {
    __shared__ int sh[256];
    int i = blockIdx.x * 256 + threadIdx.x;
    sh[threadIdx.x] = (i < n) ? cnt[i] : 0;
    __syncthreads();
    for (int o = 128; o > 0; o >>= 1) {
        if (threadIdx.x < o) sh[threadIdx.x] += sh[threadIdx.x + o];
        __syncthreads();
    }
    if (threadIdx.x == 0) bsum[blockIdx.x] = sh[0];
}

__global__ void scan_bsums(const int* __restrict__ bsum, int* boff, int nb) {
    __shared__ int sh[1024];
    int t = threadIdx.x;
    int v = (t < nb) ? bsum[t] : 0;
    sh[t] = v;
    __syncthreads();
    for (int o = 1; o < 1024; o <<= 1) {
        int u = (t >= o) ? sh[t - o] : 0;
        __syncthreads();
        sh[t] += u;
        __syncthreads();
    }
    if (t < nb) boff[t] = sh[t] - v;
}

__global__ void scan_final(const int* __restrict__ cnt, const int* __restrict__ boff,
                           int* off, int* cur, float* dinv, int n) {
    __shared__ int sh[256];
    int i = blockIdx.x * 256 + threadIdx.x;
    int v = (i < n) ? cnt[i] : 0;
    sh[threadIdx.x] = v;
    __syncthreads();
    for (int o = 1; o < 256; o <<= 1) {
        int u = (threadIdx.x >= o) ? sh[threadIdx.x - o] : 0;
        __syncthreads();
        sh[threadIdx.x] += u;
        __syncthreads();
    }
    if (i < n) {
        int excl = boff[blockIdx.x] + sh[threadIdx.x] - v;
        off[i] = excl;
        cur[i] = excl;
        dinv[i] = rsqrtf((float)(v + 1));  // +1 self loop
    }
}

__global__ void place_edges(const int* __restrict__ src, const int* __restrict__ dst,
                            int* cur, int* srcsort, int E) {
    int e = blockIdx.x * blockDim.x + threadIdx.x;
    if (e < E) {
        int d = dst[e];
        int pos = atomicAdd(&cur[d], 1);
        srcsort[pos] = src[e];
    }
}

// ====== 3xBF16 GEMM: BK=32, 3-stage cp.async, swizzled smem, templated BN ======
// Stage layout: [A_hi 8K | A_lo 8K | B_hi BN*64 | B_lo BN*64].
template <int BN>
__global__ __launch_bounds__(256, 2)
void gemm_bf16x3(const uint32_t* __restrict__ Ahi, const uint32_t* __restrict__ Alo,
                 const uint32_t* __restrict__ Bhi, const uint32_t* __restrict__ Blo,
                 float* __restrict__ C, int M, int N) {
    constexpr int MT = 2;
    constexpr int NT = BN / 16;                      // n-tiles per warp
    constexpr int NP = NT / 2;                       // ldsm pairs per warp
    constexpr int TILES = KDIM / 32;                 // 8
    constexpr int STAGES = 3;
    constexpr uint32_t A_BYTES = 128 * 64;           // 8192 per array
    constexpr uint32_t B_BYTES = (uint32_t)BN * 64;
    constexpr uint32_t STAGE_B = 2 * A_BYTES + 2 * B_BYTES;
    constexpr int AW = 2;                            // A 16B chunks per thread
    constexpr int BW = (BN * 4) / 256;               // B chunks per thread (1 or 2)

    extern __shared__ __align__(16) uint32_t smem_dyn[];

    const int tid  = threadIdx.x;
    const int wid  = tid >> 5;
    const int lane = tid & 31;
    const int g    = lane >> 2;
    const int tig  = lane & 3;
    const int q    = lane >> 3;
    const int lr   = lane & 7;
    const int row0 = blockIdx.y * 128;
    const int col0 = blockIdx.x * BN;
    const int warpM = (wid >> 1) * 32;
    const int warpN = (wid & 1) * (BN / 2);

    const uint32_t base = (uint32_t)__cvta_generic_to_shared(smem_dyn);
    const uint32_t a_hi_b = base;
    const uint32_t a_lo_b = base + A_BYTES;
    const uint32_t b_hi_b = base + 2 * A_BYTES;
    const uint32_t b_lo_b = base + 2 * A_BYTES + B_BYTES;

    // cp.async mappings
    uint32_t a_dst[AW]; size_t a_srcb[AW]; bool a_ok[AW];
#pragma unroll
    for (int j = 0; j < AW; j++) {
        int c = tid + j * 256;
        int ar = c >> 2, aq = c & 3;
        a_dst[j]  = swz(ar, aq);
        a_srcb[j] = (size_t)(row0 + ar) * KW + aq * 4;
        a_ok[j]   = (row0 + ar) < M;
    }
    uint32_t b_dst[BW]; size_t b_srcb[BW];
#pragma unroll
    for (int j = 0; j < BW; j++) {
        int c = tid + j * 256;
        int br = c >> 2, bq = c & 3;
        b_dst[j]  = swz(br, bq);
        b_srcb[j] = (size_t)(col0 + br) * KW + bq * 4;
    }

    // ldmatrix per-lane byte offsets, per k16-half h
    uint32_t a_off[MT][2], b_off[NP][2];
#pragma unroll
    for (int mt = 0; mt < MT; mt++) {
        int row = warpM + mt * 16 + (q & 1) * 8 + lr;
#pragma unroll
        for (int h = 0; h < 2; h++)
            a_off[mt][h] = swz(row, h * 2 + (q >> 1));
    }
#pragma unroll
    for (int p = 0; p < NP; p++) {
        int row = warpN + (2 * p + (q >> 1)) * 8 + lr;
#pragma unroll
        for (int h = 0; h < 2; h++)
            b_off[p][h] = swz(row, h * 2 + (q & 1));
    }

    float acc[MT][NT][4];
#pragma unroll
    for (int mt = 0; mt < MT; mt++)
#pragma unroll
        for (int nt = 0; nt < NT; nt++)
#pragma unroll
            for (int i = 0; i < 4; i++) acc[mt][nt][i] = 0.0f;

    auto issue_tile = [&](int T) {
        uint32_t so = (uint32_t)(T % STAGES) * STAGE_B;
        int kw_ = T * 16;
#pragma unroll
        for (int j = 0; j < AW; j++) {
            cp_async16(a_hi_b + so + a_dst[j], Ahi + a_srcb[j] + kw_, a_ok[j]);
            cp_async16(a_lo_b + so + a_dst[j], Alo + a_srcb[j] + kw_, a_ok[j]);
        }
#pragma unroll
        for (int j = 0; j < BW; j++) {
            cp_async16(b_hi_b + so + b_dst[j], Bhi + b_srcb[j] + kw_, true);
            cp_async16(b_lo_b + so + b_dst[j], Blo + b_srcb[j] + kw_, true);
        }
    };

    // prologue: tiles 0,1 in flight
    issue_tile(0);
    asm volatile("cp.async.commit_group;" ::: "memory");
    issue_tile(1);
    asm volatile("cp.async.commit_group;" ::: "memory");

#pragma unroll 1
    for (int t = 0; t < TILES; t++) {
        asm volatile("cp.async.wait_group 1;" ::: "memory");
        __syncthreads();   // tile t resident; stage (t+2)%3 free of readers

        if (t + 2 < TILES) {
            issue_tile(t + 2);
            asm volatile("cp.async.commit_group;" ::: "memory");
        }

        const uint32_t so = (uint32_t)(t % STAGES) * STAGE_B;
#pragma unroll
        for (int h = 0; h < 2; h++) {       // two k16 sub-steps
            uint32_t a_hi[MT][4], a_lo[MT][4];
#pragma unroll
            for (int mt = 0; mt < MT; mt++) {
                ldsm_x4(a_hi[mt], a_hi_b + so + a_off[mt][h]);
                ldsm_x4(a_lo[mt], a_lo_b + so + a_off[mt][h]);
            }
#pragma unroll
            for (int p = 0; p < NP; p++) {
                uint32_t b_hi[4], b_lo[4];
                ldsm_x4(b_hi, b_hi_b + so + b_off[p][h]);
                ldsm_x4(b_lo, b_lo_b + so + b_off[p][h]);
#pragma unroll
                for (int mt = 0; mt < MT; mt++)
#pragma unroll
                    for (int j = 0; j < 2; j++) {
                        int nt = 2 * p + j, o = j * 2;
                        mma_bf16(acc[mt][nt], a_hi[mt], b_lo[o], b_lo[o + 1]);
                        mma_bf16(acc[mt][nt], a_lo[mt], b_hi[o], b_hi[o + 1]);
                        mma_bf16(acc[mt][nt], a_hi[mt], b_hi[o], b_hi[o + 1]);
                    }
            }
        }
    }

#pragma unroll
    for (int mt = 0; mt < MT; mt++) {
        int r1 = row0 + warpM + mt * 16 + g;
        int r2 = r1 + 8;
#pragma unroll
        for (int nt = 0; nt < NT; nt++) {
            int cc = col0 + warpN + nt * 8 + 2 * tig;
            if (r1 < M)
                *(float2*)(C + (size_t)r1 * N + cc) = make_float2(acc[mt][nt][0], acc[mt][nt][1]);
            if (r2 < M)
                *(float2*)(C + (size_t)r2 * N + cc) = make_float2(acc[mt][nt][2], acc[mt][nt][3]);
        }
    }
}

// ====== layer-1 aggregate ======
__global__ void agg1_kernel(const float* __restrict__ h,
                            const int* __restrict__ srcsort,
                            const int* __restrict__ off,
                            const float* __restrict__ dinv,
                            const float* __restrict__ b1,
                            uint32_t* __restrict__ a1hi, uint32_t* __restrict__ a1lo,
                            int n, int E) {
    int node = blockIdx.x * (blockDim.x >> 5) + (threadIdx.x >> 5);
    if (node >= n) return;
    int lane = threadIdx.x & 31;

    float di = dinv[node];
    const float4* hp = (const float4*)(h + (size_t)node * D_HID);
    float4 v0 = __ldg(hp + lane);
    float4 v1 = __ldg(hp + lane + 32);
    float4 a0 = make_float4(v0.x * di, v0.y * di, v0.z * di, v0.w * di);
    float4 a1 = make_float4(v1.x * di, v1.y * di, v1.z * di, v1.w * di);

    int e0 = off[node];
    int e1 = (node + 1 < n) ? off[node + 1] : E;
    for (int e = e0; e < e1; e++) {
        int s = srcsort[e];
        float ds = __ldg(dinv + s);
        const float4* sp = (const float4*)(h + (size_t)s * D_HID);
        float4 u0 = __ldg(sp + lane);
        float4 u1 = __ldg(sp + lane + 32);
        a0.x = fmaf(u0.x, ds, a0.x); a0.y = fmaf(u0.y, ds, a0.y);
        a0.z = fmaf(u0.z, ds, a0.z); a0.w = fmaf(u0.w, ds, a0.w);
        a1.x = fmaf(u1.x, ds, a1.x); a1.y = fmaf(u1.y, ds, a1.y);
        a1.z = fmaf(u1.z, ds, a1.z); a1.w = fmaf(u1.w, ds, a1.w);
    }

    const float4* bb = (const float4*)b1;
    float4 c0 = __ldg(bb + lane);
    float4 c1 = __ldg(bb + lane + 32);
    float4 r0, r1;
    r0.x = fmaxf(fmaf(a0.x, di, c0.x), 0.0f);
    r0.y = fmaxf(fmaf(a0.y, di, c0.y), 0.0f);
    r0.z = fmaxf(fmaf(a0.z, di, c0.z), 0.0f);
    r0.w = fmaxf(fmaf(a0.w, di, c0.w), 0.0f);
    r1.x = fmaxf(fmaf(a1.x, di, c1.x), 0.0f);
    r1.y = fmaxf(fmaf(a1.y, di, c1.y), 0.0f);
    r1.z = fmaxf(fmaf(a1.z, di, c1.z), 0.0f);
    r1.w = fmaxf(fmaf(a1.w, di, c1.w), 0.0f);

    uint32_t h0a, l0a, h0b, l0b, h1a, l1a, h1b, l1b;
    split2_bf16(make_float2(r0.x, r0.y), h0a, l0a);
    split2_bf16(make_float2(r0.z, r0.w), h0b, l0b);
    split2_bf16(make_float2(r1.x, r1.y), h1a, l1a);
    split2_bf16(make_float2(r1.z, r1.w), h1b, l1b);
    uint2* ophi = (uint2*)(a1hi + (size_t)node * KW);
    uint2* oplo = (uint2*)(a1lo + (size_t)node * KW);
    ophi[lane]      = make_uint2(h0a, h0b);
    ophi[lane + 32] = make_uint2(h1a, h1b);
    oplo[lane]      = make_uint2(l0a, l0b);
    oplo[lane + 32] = make_uint2(l1a, l1b);
}

// ====== layer-2 aggregate ======
__global__ void agg2_kernel(const float* __restrict__ h,
                            const int* __restrict__ srcsort,
                            const int* __restrict__ off,
                            const float* __restrict__ dinv,
                            const float* __restrict__ b2,
                            float* __restrict__ out, int n, int E) {
    int node = blockIdx.x * (blockDim.x >> 5) + (threadIdx.x >> 5);
    if (node >= n) return;
    int lane = threadIdx.x & 31;

    float di = dinv[node];
    const float2* hp = (const float2*)(h + (size_t)node * D_CLS);
    float2 u = __ldg(hp + lane);
    float2 a = make_float2(u.x * di, u.y * di);

    int e0 = off[node];
    int e1 = (node + 1 < n) ? off[node + 1] : E;
    for (int e = e0; e < e1; e++) {
        int s = srcsort[e];
        float ds = __ldg(dinv + s);
        float2 v = __ldg(((const float2*)(h + (size_t)s * D_CLS)) + lane);
        a.x = fmaf(v.x, ds, a.x);
        a.y = fmaf(v.y, ds, a.y);
    }

    float v0 = fmaf(a.x, di, __ldg(b2 + 2 * lane));
    float v1 = fmaf(a.y, di, __ldg(b2 + 2 * lane + 1));

    float m = fmaxf(v0, v1);
#pragma unroll
    for (int o = 16; o > 0; o >>= 1) m = fmaxf(m, __shfl_xor_sync(0xFFFFFFFFu, m, o));
    float s = __expf(v0 - m) + __expf(v1 - m);
#pragma unroll
    for (int o = 16; o > 0; o >>= 1) s += __shfl_xor_sync(0xFFFFFFFFu, s, o);
    float lse = m + __logf(s);

    float2* op = (float2*)(out + (size_t)node * D_CLS);
    op[lane] = make_float2(v0 - lse, v1 - lse);
}

extern "C" void kernel_launch(void* const* d_in, const int* in_sizes, int n_in,
                              void* d_out, int out_size) {
    const float* x   = (const float*)d_in[0];
    const int*   ei  = (const int*)d_in[1];   // JAX int64 request silently -> int32
    const float* W1  = (const float*)d_in[2];
    const float* b1  = (const float*)d_in[3];
    const float* W2  = (const float*)d_in[4];
    const float* b2  = (const float*)d_in[5];
    float*       out = (float*)d_out;

    const int n = in_sizes[0] / D_IN;
    const int E = in_sizes[1] / 2;
    const int* src = ei;
    const int* dst = ei + E;

    float *h1, *h2, *dinv;
    uint32_t *xhi, *xlo, *a1hi, *a1lo, *w1hi, *w1lo, *w2hi, *w2lo;
    int *cnt, *off, *cur, *srcsort, *bsum, *boff;
    cudaGetSymbolAddress((void**)&h1,   g_h1);
    cudaGetSymbolAddress((void**)&h2,   g_h2);
    cudaGetSymbolAddress((void**)&xhi,  g_xhi);
    cudaGetSymbolAddress((void**)&xlo,  g_xlo);
    cudaGetSymbolAddress((void**)&a1hi, g_a1hi);
    cudaGetSymbolAddress((void**)&a1lo, g_a1lo);
    cudaGetSymbolAddress((void**)&w1hi, g_w1hi);
    cudaGetSymbolAddress((void**)&w1lo, g_w1lo);
    cudaGetSymbolAddress((void**)&w2hi, g_w2hi);
    cudaGetSymbolAddress((void**)&w2lo, g_w2lo);
    cudaGetSymbolAddress((void**)&dinv, g_dinv);
    cudaGetSymbolAddress((void**)&cnt,  g_cnt);
    cudaGetSymbolAddress((void**)&off,  g_off);
    cudaGetSymbolAddress((void**)&cur,  g_cur);
    cudaGetSymbolAddress((void**)&srcsort, g_srcsort);
    cudaGetSymbolAddress((void**)&bsum, g_bsum);
    cudaGetSymbolAddress((void**)&boff, g_boff);

    const int NB = (n + 255) / 256;   // <= 1024
    const int MB = (n + 127) / 128;
    const long nwords = (long)n * KW;

    // GEMM1: BN=128, 3 stages x 32KB = 96KB; GEMM2: BN=64, 3 x 24KB = 72KB
    const int SMEM_G1 = 3 * (2 * 128 * 64 + 2 * 128 * 64);   // 98304
    const int SMEM_G2 = 3 * (2 * 128 * 64 + 2 * 64 * 64);    // 73728
    cudaFuncSetAttribute(gemm_bf16x3<128>, cudaFuncAttributeMaxDynamicSharedMemorySize, SMEM_G1);
    cudaFuncSetAttribute(gemm_bf16x3<64>,  cudaFuncAttributeMaxDynamicSharedMemorySize, SMEM_G2);

    // 1: split x (+ zero cnt), 2: split weights, 3: degree count
    split_x<<<2048, 256>>>(x, xhi, xlo, cnt, n, nwords);
    split_w<<<(D_HID * KW + D_CLS * KW + 255) / 256, 256>>>(W1, W2, w1hi, w1lo, w2hi, w2lo);
    count_dst<<<(E + 255) / 256, 256>>>(dst, cnt, E);

    // 4: GEMM1 (profiler capture slot): h1 = x @ W1
    gemm_bf16x3<128><<<dim3(D_HID / 128, MB), 256, SMEM_G1>>>(xhi, xlo, w1hi, w1lo, h1, n, D_HID);

    // CSR (+ dinv fused into scan_final)
    block_sums <<<NB, 256>>>(cnt, bsum, n);
    scan_bsums <<<1, 1024>>>(bsum, boff, NB);
    scan_final <<<NB, 256>>>(cnt, boff, off, cur, dinv, n);
    place_edges<<<(E + 255) / 256, 256>>>(src, dst, cur, srcsort, E);

    // agg1: normalize+aggregate+bias+relu, emit split bf16
    agg1_kernel<<<(n + 7) / 8, 256>>>(h1, srcsort, off, dinv, b1, a1hi, a1lo, n, E);

    // GEMM2: h2 = agg1 @ W2
    gemm_bf16x3<64><<<dim3(D_CLS / 64, MB), 256, SMEM_G2>>>(a1hi, a1lo, w2hi, w2lo, h2, n, D_CLS);

    // agg2: normalize+aggregate+bias+log_softmax
    agg2_kernel<<<(n + 7) / 8, 256>>>(h2, srcsort, off, dinv, b2, out, n, E);
}

// round 16
// speedup vs baseline: 1.0317x; 1.0317x over previous
#include <cuda_runtime.h>
#include <cuda_bf16.h>
#include <math.h>
#include <stdint.h>

// ---------------- problem constants ----------------
#define MAX_NODES 100000
#define MAX_EDGES 2000000
#define D_IN  256
#define D_HID 256
#define D_CLS 64
#define KDIM  256
#define KW    (KDIM / 2)   // packed bf16x2 words per row

// ---------------- scratch (static, no allocs) ----------------
__device__ float    g_h1  [(size_t)MAX_NODES * D_HID];
__device__ float    g_h2  [(size_t)MAX_NODES * D_CLS];
__device__ uint32_t g_xhi [(size_t)MAX_NODES * KW];
__device__ uint32_t g_xlo [(size_t)MAX_NODES * KW];
__device__ uint32_t g_a1hi[(size_t)MAX_NODES * KW];
__device__ uint32_t g_a1lo[(size_t)MAX_NODES * KW];
__device__ uint32_t g_w1hi[D_HID * KW], g_w1lo[D_HID * KW];
__device__ uint32_t g_w2hi[D_CLS * KW], g_w2lo[D_CLS * KW];
__device__ float    g_dinv[MAX_NODES];
__device__ int      g_cnt [MAX_NODES];
__device__ int      g_off [MAX_NODES];
__device__ int      g_cur [MAX_NODES];
__device__ int      g_srcsort[MAX_EDGES];
__device__ int      g_bsum[1024];
__device__ int      g_boff[1024];

// ---------------- helpers ----------------
__device__ __forceinline__ void split2_bf16(float2 v, uint32_t& hi, uint32_t& lo) {
    __nv_bfloat16 hx = __float2bfloat16(v.x);
    __nv_bfloat16 hy = __float2bfloat16(v.y);
    __nv_bfloat16 lx = __float2bfloat16(v.x - __bfloat162float(hx));
    __nv_bfloat16 ly = __float2bfloat16(v.y - __bfloat162float(hy));
    hi = (uint32_t)__bfloat16_as_ushort(hx) | ((uint32_t)__bfloat16_as_ushort(hy) << 16);
    lo = (uint32_t)__bfloat16_as_ushort(lx) | ((uint32_t)__bfloat16_as_ushort(ly) << 16);
}

__device__ __forceinline__ void cp_async16(uint32_t dst, const void* src, bool pred) {
    int sz = pred ? 16 : 0;
    asm volatile("cp.async.cg.shared.global [%0], [%1], 16, %2;"
                 :: "r"(dst), "l"(src), "r"(sz) : "memory");
}

__device__ __forceinline__ void ldsm_x4(uint32_t r[4], uint32_t addr) {
    asm volatile("ldmatrix.sync.aligned.m8n8.x4.shared.b16 {%0,%1,%2,%3}, [%4];"
                 : "=r"(r[0]), "=r"(r[1]), "=r"(r[2]), "=r"(r[3]) : "r"(addr));
}

__device__ __forceinline__ void mma_bf16(float c[4], const uint32_t a[4],
                                         uint32_t b0, uint32_t b1) {
    asm volatile(
        "mma.sync.aligned.m16n8k16.row.col.f32.bf16.bf16.f32 "
        "{%0,%1,%2,%3}, {%4,%5,%6,%7}, {%8,%9}, {%0,%1,%2,%3};"
        : "+f"(c[0]), "+f"(c[1]), "+f"(c[2]), "+f"(c[3])
        : "r"(a[0]), "r"(a[1]), "r"(a[2]), "r"(a[3]), "r"(b0), "r"(b1));
}

// swizzled byte offset: 64B rows of 4x16B chunks, chunk column permuted by row
// so each ldmatrix phase (8 consecutive rows) hits 8 distinct 16B bank-groups.
__device__ __forceinline__ uint32_t swz(int row, int q) {
    return (uint32_t)(row * 64 + ((q ^ ((row >> 1) & 3)) * 16));
}

// ---------------- pre-split kernels ----------------
__global__ void split_x(const float* __restrict__ x, uint32_t* __restrict__ xhi,
                        uint32_t* __restrict__ xlo, int* __restrict__ cnt,
                        int n, long nw) {
    long i0 = (long)blockIdx.x * blockDim.x + threadIdx.x;
    if (i0 < n) cnt[i0] = 0;
    long stride = (long)gridDim.x * blockDim.x;
    for (long i = i0; i < nw; i += stride) {
        float2 v = ((const float2*)x)[i];
        uint32_t hi, lo;
        split2_bf16(v, hi, lo);
        xhi[i] = hi;
        xlo[i] = lo;
    }
}

__global__ void split_w(const float* __restrict__ W1, const float* __restrict__ W2,
                        uint32_t* w1hi, uint32_t* w1lo,
                        uint32_t* w2hi, uint32_t* w2lo) {
    int i = blockIdx.x * 256 + threadIdx.x;
    if (i < D_HID * KW) {
        int nn = i >> 7, w = i & (KW - 1);
        float2 v = make_float2(W1[(2 * w) * D_HID + nn], W1[(2 * w + 1) * D_HID + nn]);
        uint32_t hi, lo;
        split2_bf16(v, hi, lo);
        w1hi[i] = hi; w1lo[i] = lo;
    } else if (i < D_HID * KW + D_CLS * KW) {
        int j = i - D_HID * KW;
        int nn = j >> 7, w = j & (KW - 1);
        float2 v = make_float2(W2[(2 * w) * D_CLS + nn], W2[(2 * w + 1) * D_CLS + nn]);
        uint32_t hi, lo;
        split2_bf16(v, hi, lo);
        w2hi[j] = hi; w2lo[j] = lo;
    }
}

// ---------------- CSR build ----------------
__global__ void count_dst(const int* __restrict__ dst, int* cnt, int E) {
    int e = blockIdx.x * blockDim.x + threadIdx.x;
    if (e < E) atomicAdd(&cnt[dst[e]], 1);
}

__global__ void block_sums(const int* __restrict__ cnt, int* bsum, int n) {
    __shared__ int sh[256];
    int i = blockIdx.x * 256 + threadIdx.x;
    sh[threadIdx.x] = (i < n) ? cnt[i] : 0;
    __syncthreads();
    for (int o = 128; o > 0; o >>= 1) {
        if (threadIdx.x < o) sh[threadIdx.x] += sh[threadIdx.x + o];
        __syncthreads();
    }
    if (threadIdx.x == 0) bsum[blockIdx.x] = sh[0];
}

__global__ void scan_bsums(const int* __restrict__ bsum, int* boff, int nb) {
    __shared__ int sh[1024];
    int t = threadIdx.x;
    int v = (t < nb) ? bsum[t] : 0;
    sh[t] = v;
    __syncthreads();
    for (int o = 1; o < 1024; o <<= 1) {
        int u = (t >= o) ? sh[t - o] : 0;
        __syncthreads();
        sh[t] += u;
        __syncthreads();
    }
    if (t < nb) boff[t] = sh[t] - v;
}

__global__ void scan_final(const int* __restrict__ cnt, const int* __restrict__ boff,
                           int* off, int* cur, float* dinv, int n) {
    __shared__ int sh[256];
    int i = blockIdx.x * 256 + threadIdx.x;
    int v = (i < n) ? cnt[i] : 0;
    sh[threadIdx.x] = v;
    __syncthreads();
    for (int o = 1; o < 256; o <<= 1) {
        int u = (threadIdx.x >= o) ? sh[threadIdx.x - o] : 0;
        __syncthreads();
        sh[threadIdx.x] += u;
        __syncthreads();
    }
    if (i < n) {
        int excl = boff[blockIdx.x] + sh[threadIdx.x] - v;
        off[i] = excl;
        cur[i] = excl;
        dinv[i] = rsqrtf((float)(v + 1));  // +1 self loop
    }
}

__global__ void place_edges(const int* __restrict__ src, const int* __restrict__ dst,
                            int* cur, int* srcsort, int E) {
    int e = blockIdx.x * blockDim.x + threadIdx.x;
    if (e < E) {
        int d = dst[e];
        int pos = atomicAdd(&cur[d], 1);
        srcsort[pos] = src[e];
    }
}

// ====== 3xBF16 GEMM: BK=32, 3-stage cp.async, swizzled smem, templated BN ======
// Stage layout: [A_hi 8K | A_lo 8K | B_hi BN*64 | B_lo BN*64].
template <int BN>
__global__ __launch_bounds__(256, (BN == 64) ? 3 : 2)
void gemm_bf16x3(const uint32_t* __restrict__ Ahi, const uint32_t* __restrict__ Alo,
                 const uint32_t* __restrict__ Bhi, const uint32_t* __restrict__ Blo,
                 float* __restrict__ C, int M, int N) {
    constexpr int MT = 2;
    constexpr int NT = BN / 16;                      // n-tiles per warp
    constexpr int NP = NT / 2;                       // ldsm pairs per warp
    constexpr int TILES = KDIM / 32;                 // 8
    constexpr int STAGES = 3;
    constexpr uint32_t A_BYTES = 128 * 64;           // 8192 per array
    constexpr uint32_t B_BYTES = (uint32_t)BN * 64;
    constexpr uint32_t STAGE_B = 2 * A_BYTES + 2 * B_BYTES;
    constexpr int AW = 2;                            // A 16B chunks per thread
    constexpr int BW = (BN * 4) / 256;               // B chunks per thread (1 or 2)

    extern __shared__ __align__(16) uint32_t smem_dyn[];

    const int tid  = threadIdx.x;
    const int wid  = tid >> 5;
    const int lane = tid & 31;
    const int g    = lane >> 2;
    const int tig  = lane & 3;
    const int q    = lane >> 3;
    const int lr   = lane & 7;
    const int row0 = blockIdx.y * 128;
    const int col0 = blockIdx.x * BN;
    const int warpM = (wid >> 1) * 32;
    const int warpN = (wid & 1) * (BN / 2);

    const uint32_t base = (uint32_t)__cvta_generic_to_shared(smem_dyn);
    const uint32_t a_hi_b = base;
    const uint32_t a_lo_b = base + A_BYTES;
    const uint32_t b_hi_b = base + 2 * A_BYTES;
    const uint32_t b_lo_b = base + 2 * A_BYTES + B_BYTES;

    // cp.async mappings
    uint32_t a_dst[AW]; size_t a_srcb[AW]; bool a_ok[AW];
#pragma unroll
    for (int j = 0; j < AW; j++) {
        int c = tid + j * 256;
        int ar = c >> 2, aq = c & 3;
        a_dst[j]  = swz(ar, aq);
        a_srcb[j] = (size_t)(row0 + ar) * KW + aq * 4;
        a_ok[j]   = (row0 + ar) < M;
    }
    uint32_t b_dst[BW]; size_t b_srcb[BW];
#pragma unroll
    for (int j = 0; j < BW; j++) {
        int c = tid + j * 256;
        int br = c >> 2, bq = c & 3;
        b_dst[j]  = swz(br, bq);
        b_srcb[j] = (size_t)(col0 + br) * KW + bq * 4;
    }

    // ldmatrix per-lane byte offsets, per k16-half h
    uint32_t a_off[MT][2], b_off[NP][2];
#pragma unroll
    for (int mt = 0; mt < MT; mt++) {
        int row = warpM + mt * 16 + (q & 1) * 8 + lr;
#pragma unroll
        for (int h = 0; h < 2; h++)
            a_off[mt][h] = swz(row, h * 2 + (q >> 1));
    }
#pragma unroll
    for (int p = 0; p < NP; p++) {
        int row = warpN + (2 * p + (q >> 1)) * 8 + lr;
#pragma unroll
        for (int h = 0; h < 2; h++)
            b_off[p][h] = swz(row, h * 2 + (q & 1));
    }

    float acc[MT][NT][4];
#pragma unroll
    for (int mt = 0; mt < MT; mt++)
#pragma unroll
        for (int nt = 0; nt < NT; nt++)
#pragma unroll
            for (int i = 0; i < 4; i++) acc[mt][nt][i] = 0.0f;

    auto issue_tile = [&](int T) {
        uint32_t so = (uint32_t)(T % STAGES) * STAGE_B;
        int kw_ = T * 16;
#pragma unroll
        for (int j = 0; j < AW; j++) {
            cp_async16(a_hi_b + so + a_dst[j], Ahi + a_srcb[j] + kw_, a_ok[j]);
            cp_async16(a_lo_b + so + a_dst[j], Alo + a_srcb[j] + kw_, a_ok[j]);
        }
#pragma unroll
        for (int j = 0; j < BW; j++) {
            cp_async16(b_hi_b + so + b_dst[j], Bhi + b_srcb[j] + kw_, true);
            cp_async16(b_lo_b + so + b_dst[j], Blo + b_srcb[j] + kw_, true);
        }
    };

    // prologue: tiles 0,1 in flight
    issue_tile(0);
    asm volatile("cp.async.commit_group;" ::: "memory");
    issue_tile(1);
    asm volatile("cp.async.commit_group;" ::: "memory");

#pragma unroll 1
    for (int t = 0; t < TILES; t++) {
        asm volatile("cp.async.wait_group 1;" ::: "memory");
        __syncthreads();   // tile t resident; stage (t+2)%3 free of readers

        if (t + 2 < TILES) {
            issue_tile(t + 2);
            asm volatile("cp.async.commit_group;" ::: "memory");
        }

        const uint32_t so = (uint32_t)(t % STAGES) * STAGE_B;
#pragma unroll
        for (int h = 0; h < 2; h++) {       // two k16 sub-steps
            uint32_t a_hi[MT][4], a_lo[MT][4];
#pragma unroll
            for (int mt = 0; mt < MT; mt++) {
                ldsm_x4(a_hi[mt], a_hi_b + so + a_off[mt][h]);
                ldsm_x4(a_lo[mt], a_lo_b + so + a_off[mt][h]);
            }
#pragma unroll
            for (int p = 0; p < NP; p++) {
                uint32_t b_hi[4], b_lo[4];
                ldsm_x4(b_hi, b_hi_b + so + b_off[p][h]);
                ldsm_x4(b_lo, b_lo_b + so + b_off[p][h]);
#pragma unroll
                for (int mt = 0; mt < MT; mt++)
#pragma unroll
                    for (int j = 0; j < 2; j++) {
                        int nt = 2 * p + j, o = j * 2;
                        mma_bf16(acc[mt][nt], a_hi[mt], b_lo[o], b_lo[o + 1]);
                        mma_bf16(acc[mt][nt], a_lo[mt], b_hi[o], b_hi[o + 1]);
                        mma_bf16(acc[mt][nt], a_hi[mt], b_hi[o], b_hi[o + 1]);
                    }
            }
        }
    }

#pragma unroll
    for (int mt = 0; mt < MT; mt++) {
        int r1 = row0 + warpM + mt * 16 + g;
        int r2 = r1 + 8;
#pragma unroll
        for (int nt = 0; nt < NT; nt++) {
            int cc = col0 + warpN + nt * 8 + 2 * tig;
            if (r1 < M)
                *(float2*)(C + (size_t)r1 * N + cc) = make_float2(acc[mt][nt][0], acc[mt][nt][1]);
            if (r2 < M)
                *(float2*)(C + (size_t)r2 * N + cc) = make_float2(acc[mt][nt][2], acc[mt][nt][3]);
        }
    }
}

// ====== layer-1 aggregate ======
__global__ void agg1_kernel(const float* __restrict__ h,
                            const int* __restrict__ srcsort,
                            const int* __restrict__ off,
                            const float* __restrict__ dinv,
                            const float* __restrict__ b1,
                            uint32_t* __restrict__ a1hi, uint32_t* __restrict__ a1lo,
                            int n, int E) {
    int node = blockIdx.x * (blockDim.x >> 5) + (threadIdx.x >> 5);
    if (node >= n) return;
    int lane = threadIdx.x & 31;

    float di = dinv[node];
    const float4* hp = (const float4*)(h + (size_t)node * D_HID);
    float4 v0 = __ldg(hp + lane);
    float4 v1 = __ldg(hp + lane + 32);
    float4 a0 = make_float4(v0.x * di, v0.y * di, v0.z * di, v0.w * di);
    float4 a1 = make_float4(v1.x * di, v1.y * di, v1.z * di, v1.w * di);

    int e0 = off[node];
    int e1 = (node + 1 < n) ? off[node + 1] : E;
    for (int e = e0; e < e1; e++) {
        int s = srcsort[e];
        float ds = __ldg(dinv + s);
        const float4* sp = (const float4*)(h + (size_t)s * D_HID);
        float4 u0 = __ldg(sp + lane);
        float4 u1 = __ldg(sp + lane + 32);
        a0.x = fmaf(u0.x, ds, a0.x); a0.y = fmaf(u0.y, ds, a0.y);
        a0.z = fmaf(u0.z, ds, a0.z); a0.w = fmaf(u0.w, ds, a0.w);
        a1.x = fmaf(u1.x, ds, a1.x); a1.y = fmaf(u1.y, ds, a1.y);
        a1.z = fmaf(u1.z, ds, a1.z); a1.w = fmaf(u1.w, ds, a1.w);
    }

    const float4* bb = (const float4*)b1;
    float4 c0 = __ldg(bb + lane);
    float4 c1 = __ldg(bb + lane + 32);
    float4 r0, r1;
    r0.x = fmaxf(fmaf(a0.x, di, c0.x), 0.0f);
    r0.y = fmaxf(fmaf(a0.y, di, c0.y), 0.0f);
    r0.z = fmaxf(fmaf(a0.z, di, c0.z), 0.0f);
    r0.w = fmaxf(fmaf(a0.w, di, c0.w), 0.0f);
    r1.x = fmaxf(fmaf(a1.x, di, c1.x), 0.0f);
    r1.y = fmaxf(fmaf(a1.y, di, c1.y), 0.0f);
    r1.z = fmaxf(fmaf(a1.z, di, c1.z), 0.0f);
    r1.w = fmaxf(fmaf(a1.w, di, c1.w), 0.0f);

    uint32_t h0a, l0a, h0b, l0b, h1a, l1a, h1b, l1b;
    split2_bf16(make_float2(r0.x, r0.y), h0a, l0a);
    split2_bf16(make_float2(r0.z, r0.w), h0b, l0b);
    split2_bf16(make_float2(r1.x, r1.y), h1a, l1a);
    split2_bf16(make_float2(r1.z, r1.w), h1b, l1b);
    uint2* ophi = (uint2*)(a1hi + (size_t)node * KW);
    uint2* oplo = (uint2*)(a1lo + (size_t)node * KW);
    ophi[lane]      = make_uint2(h0a, h0b);
    ophi[lane + 32] = make_uint2(h1a, h1b);
    oplo[lane]      = make_uint2(l0a, l0b);
    oplo[lane + 32] = make_uint2(l1a, l1b);
}

// ====== layer-2 aggregate ======
__global__ void agg2_kernel(const float* __restrict__ h,
                            const int* __restrict__ srcsort,
                            const int* __restrict__ off,
                            const float* __restrict__ dinv,
                            const float* __restrict__ b2,
                            float* __restrict__ out, int n, int E) {
    int node = blockIdx.x * (blockDim.x >> 5) + (threadIdx.x >> 5);
    if (node >= n) return;
    int lane = threadIdx.x & 31;

    float di = dinv[node];
    const float2* hp = (const float2*)(h + (size_t)node * D_CLS);
    float2 u = __ldg(hp + lane);
    float2 a = make_float2(u.x * di, u.y * di);

    int e0 = off[node];
    int e1 = (node + 1 < n) ? off[node + 1] : E;
    for (int e = e0; e < e1; e++) {
        int s = srcsort[e];
        float ds = __ldg(dinv + s);
        float2 v = __ldg(((const float2*)(h + (size_t)s * D_CLS)) + lane);
        a.x = fmaf(v.x, ds, a.x);
        a.y = fmaf(v.y, ds, a.y);
    }

    float v0 = fmaf(a.x, di, __ldg(b2 + 2 * lane));
    float v1 = fmaf(a.y, di, __ldg(b2 + 2 * lane + 1));

    float m = fmaxf(v0, v1);
#pragma unroll
    for (int o = 16; o > 0; o >>= 1) m = fmaxf(m, __shfl_xor_sync(0xFFFFFFFFu, m, o));
    float s = __expf(v0 - m) + __expf(v1 - m);
#pragma unroll
    for (int o = 16; o > 0; o >>= 1) s += __shfl_xor_sync(0xFFFFFFFFu, s, o);
    float lse = m + __logf(s);

    float2* op = (float2*)(out + (size_t)node * D_CLS);
    op[lane] = make_float2(v0 - lse, v1 - lse);
}

extern "C" void kernel_launch(void* const* d_in, const int* in_sizes, int n_in,
                              void* d_out, int out_size) {
    const float* x   = (const float*)d_in[0];
    const int*   ei  = (const int*)d_in[1];   // JAX int64 request silently -> int32
    const float* W1  = (const float*)d_in[2];
    const float* b1  = (const float*)d_in[3];
    const float* W2  = (const float*)d_in[4];
    const float* b2  = (const float*)d_in[5];
    float*       out = (float*)d_out;

    const int n = in_sizes[0] / D_IN;
    const int E = in_sizes[1] / 2;
    const int* src = ei;
    const int* dst = ei + E;

    float *h1, *h2, *dinv;
    uint32_t *xhi, *xlo, *a1hi, *a1lo, *w1hi, *w1lo, *w2hi, *w2lo;
    int *cnt, *off, *cur, *srcsort, *bsum, *boff;
    cudaGetSymbolAddress((void**)&h1,   g_h1);
    cudaGetSymbolAddress((void**)&h2,   g_h2);
    cudaGetSymbolAddress((void**)&xhi,  g_xhi);
    cudaGetSymbolAddress((void**)&xlo,  g_xlo);
    cudaGetSymbolAddress((void**)&a1hi, g_a1hi);
    cudaGetSymbolAddress((void**)&a1lo, g_a1lo);
    cudaGetSymbolAddress((void**)&w1hi, g_w1hi);
    cudaGetSymbolAddress((void**)&w1lo, g_w1lo);
    cudaGetSymbolAddress((void**)&w2hi, g_w2hi);
    cudaGetSymbolAddress((void**)&w2lo, g_w2lo);
    cudaGetSymbolAddress((void**)&dinv, g_dinv);
    cudaGetSymbolAddress((void**)&cnt,  g_cnt);
    cudaGetSymbolAddress((void**)&off,  g_off);
    cudaGetSymbolAddress((void**)&cur,  g_cur);
    cudaGetSymbolAddress((void**)&srcsort, g_srcsort);
    cudaGetSymbolAddress((void**)&bsum, g_bsum);
    cudaGetSymbolAddress((void**)&boff, g_boff);

    const int NB = (n + 255) / 256;   // <= 1024
    const int MB = (n + 127) / 128;
    const long nwords = (long)n * KW;

    // side stream + fork/join events (created once, on the uncaptured first call)
    static cudaStream_t s2 = nullptr;
    static cudaEvent_t evFork = nullptr, evJoin = nullptr;
    if (s2 == nullptr) {
        cudaStreamCreateWithFlags(&s2, cudaStreamNonBlocking);
        cudaEventCreateWithFlags(&evFork, cudaEventDisableTiming);
        cudaEventCreateWithFlags(&evJoin, cudaEventDisableTiming);
    }

    const int SMEM_G = 3 * (2 * 128 * 64 + 2 * 64 * 64);    // 73728 (BN=64)
    cudaFuncSetAttribute(gemm_bf16x3<64>, cudaFuncAttributeMaxDynamicSharedMemorySize, SMEM_G);

    // main stream: splits
    split_x<<<2048, 256>>>(x, xhi, xlo, cnt, n, nwords);
    split_w<<<(D_HID * KW + D_CLS * KW + 255) / 256, 256>>>(W1, W2, w1hi, w1lo, w2hi, w2lo);

    // fork: CSR chain on side stream, concurrent with GEMM1
    cudaEventRecord(evFork, 0);
    cudaStreamWaitEvent(s2, evFork, 0);
    count_dst  <<<(E + 255) / 256, 256, 0, s2>>>(dst, cnt, E);
    block_sums <<<NB, 256, 0, s2>>>(cnt, bsum, n);
    scan_bsums <<<1, 1024, 0, s2>>>(bsum, boff, NB);
    scan_final <<<NB, 256, 0, s2>>>(cnt, boff, off, cur, dinv, n);
    place_edges<<<(E + 255) / 256, 256, 0, s2>>>(src, dst, cur, srcsort, E);
    cudaEventRecord(evJoin, s2);

    // main stream: GEMM1 overlaps the CSR chain
    gemm_bf16x3<64><<<dim3(D_HID / 64, MB), 256, SMEM_G>>>(xhi, xlo, w1hi, w1lo, h1, n, D_HID);

    // join: agg1 needs both GEMM1 (main) and CSR (side)
    cudaStreamWaitEvent(0, evJoin, 0);

    agg1_kernel<<<(n + 7) / 8, 256>>>(h1, srcsort, off, dinv, b1, a1hi, a1lo, n, E);
    gemm_bf16x3<64><<<dim3(D_CLS / 64, MB), 256, SMEM_G>>>(a1hi, a1lo, w2hi, w2lo, h2, n, D_CLS);
    agg2_kernel<<<(n + 7) / 8, 256>>>(h2, srcsort, off, dinv, b2, out, n, E);
}